// round 2
// baseline (speedup 1.0000x reference)
#include <cuda_runtime.h>
#include <cuda_bf16.h>
#include <cstdint>

// ============================================================================
// sLSTM cell, B=4096, D=4096 on sm_103a WITHOUT tcgen05 (toolchain compiles
// through compute_103 virtual arch -> only sm_80-era tensor PTX available).
// G = [x | h^T] (4096 x 8192) @ Wcat (8192 x 16384), gates [i,f,o,c] along N.
// bf16 2-term split (hi+lo): G = Ahi*Bhi + Alo*Bhi + Ahi*Blo  (fp32 accum).
// GEMM: cp.async 4-stage pipeline + ldmatrix + mma.sync.m16n8k16.bf16.
// ============================================================================

#define BDIM 4096
#define DDIM 4096
#define KDIM 8192
#define NDIM 16384

#define BM 128
#define BN 128
#define BK 32
#define STAGES 4
#define NITER (KDIM / BK)          // 256
#define TILEB (BM * BK * 2)        // 8192 bytes per operand tile
#define STAGEB (4 * TILEB)         // 32768 (Ahi,Alo,Bhi,Blo)
#define SMEMB (STAGES * STAGEB)    // 131072

// -------------------- scratch (module-scope, allowed) -----------------------
__device__ __align__(256) __nv_bfloat16 g_Ahi[(size_t)BDIM * KDIM];
__device__ __align__(256) __nv_bfloat16 g_Alo[(size_t)BDIM * KDIM];
__device__ __align__(256) __nv_bfloat16 g_Bhi[(size_t)NDIM * KDIM];
__device__ __align__(256) __nv_bfloat16 g_Blo[(size_t)NDIM * KDIM];
__device__ __align__(256) float         g_G  [(size_t)BDIM * NDIM];

// -------------------- PTX helpers -------------------------------------------
__device__ __forceinline__ uint32_t smem_u32(const void* p) {
    uint32_t a;
    asm("{ .reg .u64 t; cvta.to.shared.u64 t, %1; cvt.u32.u64 %0, t; }"
        : "=r"(a) : "l"(p));
    return a;
}
__device__ __forceinline__ void cp_async16(uint32_t dst, const void* src) {
    asm volatile("cp.async.cg.shared.global [%0], [%1], 16;" :: "r"(dst), "l"(src) : "memory");
}
#define CP_COMMIT() asm volatile("cp.async.commit_group;" ::: "memory")
#define CP_WAIT(N)  asm volatile("cp.async.wait_group %0;" :: "n"(N) : "memory")

__device__ __forceinline__ void ldsm4(uint32_t& r0, uint32_t& r1, uint32_t& r2, uint32_t& r3,
                                      uint32_t addr) {
    asm volatile("ldmatrix.sync.aligned.m8n8.x4.shared.b16 {%0,%1,%2,%3}, [%4];"
                 : "=r"(r0), "=r"(r1), "=r"(r2), "=r"(r3) : "r"(addr));
}
__device__ __forceinline__ void mma16816(float* c, const uint32_t* a, const uint32_t* b) {
    asm volatile(
        "mma.sync.aligned.m16n8k16.row.col.f32.bf16.bf16.f32 "
        "{%0,%1,%2,%3}, {%4,%5,%6,%7}, {%8,%9}, {%0,%1,%2,%3};"
        : "+f"(c[0]), "+f"(c[1]), "+f"(c[2]), "+f"(c[3])
        : "r"(a[0]), "r"(a[1]), "r"(a[2]), "r"(a[3]), "r"(b[0]), "r"(b[1]));
}

// swizzled byte offset within one [128][BK] bf16 tile (64B rows).
// chunk16 (0..3) XOR'd with bits (row>>1)&3 -> conflict-free for cp.async
// writes and for ldmatrix 8-row reads (proven: even/odd rows each cover all
// four 16B chunks of their 64B row half within a 128B phase).
__device__ __forceinline__ uint32_t sw_off(uint32_t row, uint32_t c16) {
    return row * 64u + ((c16 ^ ((row >> 1) & 3u)) << 4);
}

// -------------------- prep kernels ------------------------------------------
__device__ __forceinline__ void split_storeA(float v, size_t o) {
    __nv_bfloat16 hi = __float2bfloat16(v);
    g_Ahi[o] = hi;
    g_Alo[o] = __float2bfloat16(v - __bfloat162float(hi));
}

__global__ void __launch_bounds__(256) prep_x(const float* __restrict__ x) {
    size_t i = (size_t)blockIdx.x * 256 + threadIdx.x;   // 16,777,216
    int b = (int)(i >> 12), k = (int)(i & 4095);
    split_storeA(x[i], (size_t)b * KDIM + k);
}

__global__ void __launch_bounds__(256) prep_h(const float* __restrict__ h) {
    __shared__ float t[32][33];
    int tx = threadIdx.x, ty = threadIdx.y;
    int b0 = blockIdx.x * 32, r0 = blockIdx.y * 32;
#pragma unroll
    for (int i = 0; i < 4; i++)
        t[ty + 8 * i][tx] = h[(size_t)(r0 + ty + 8 * i) * DDIM + b0 + tx];
    __syncthreads();
#pragma unroll
    for (int i = 0; i < 4; i++) {
        size_t o = (size_t)(b0 + ty + 8 * i) * KDIM + 4096 + r0 + tx;
        split_storeA(t[tx][ty + 8 * i], o);
    }
}

__global__ void __launch_bounds__(256) prep_w(
    const float* w0, const float* w1, const float* w2, const float* w3,
    const float* u0, const float* u1, const float* u2, const float* u3) {
    __shared__ float t[32][33];
    int tx = threadIdx.x, ty = threadIdx.y;
    int z = blockIdx.z;
    const float* arr[8] = {w0, w1, w2, w3, u0, u1, u2, u3};
    const float* src = arr[z];
    int gate = z & 3, half = z >> 2;
    int d0 = blockIdx.x * 32, k0 = blockIdx.y * 32;
#pragma unroll
    for (int i = 0; i < 4; i++)
        t[ty + 8 * i][tx] = src[(size_t)(k0 + ty + 8 * i) * DDIM + d0 + tx];
    __syncthreads();
#pragma unroll
    for (int i = 0; i < 4; i++) {
        float v = t[tx][ty + 8 * i];
        size_t o = (size_t)(gate * 4096 + d0 + ty + 8 * i) * KDIM + half * 4096 + k0 + tx;
        __nv_bfloat16 hi = __float2bfloat16(v);
        g_Bhi[o] = hi;
        g_Blo[o] = __float2bfloat16(v - __bfloat162float(hi));
    }
}

// -------------------- GEMM kernel -------------------------------------------
__device__ __forceinline__ void fill_stage(uint32_t sbase, int kblk, int m0, int n0) {
    const int tid = threadIdx.x;
#pragma unroll
    for (int j = 0; j < 2; j++) {
        int q = tid + 256 * j;          // 16B chunk id, 0..511
        int row = q >> 2;               // 0..127
        int c = q & 3;                  // 16B chunk within 64B row
        uint32_t off = sw_off(row, c);
        size_t ka = (size_t)(m0 + row) * KDIM + kblk + c * 8;
        size_t kb = (size_t)(n0 + row) * KDIM + kblk + c * 8;
        cp_async16(sbase + 0 * TILEB + off, &g_Ahi[ka]);
        cp_async16(sbase + 1 * TILEB + off, &g_Alo[ka]);
        cp_async16(sbase + 2 * TILEB + off, &g_Bhi[kb]);
        cp_async16(sbase + 3 * TILEB + off, &g_Blo[kb]);
    }
}

__global__ void __launch_bounds__(256, 1) slstm_gemm() {
    extern __shared__ char smem[];
    uint32_t sb = smem_u32(smem);
    const int tid = threadIdx.x;
    const int wid = tid >> 5;
    const int lane = tid & 31;
    const int wm = wid >> 1;            // 0..3  (M warp, 32 rows)
    const int wn = wid & 1;             // 0..1  (N warp, 64 cols)

    // supertile rasterization for L2 reuse
    const int grid_m = BDIM / BM, grid_n = NDIM / BN;   // 32, 128
    const int GROUP = 8;
    int pid = blockIdx.x;
    int npg = GROUP * grid_n;
    int first_m = (pid / npg) * GROUP;
    int gs = min(grid_m - first_m, GROUP);
    int pig = pid % npg;
    int m0 = (first_m + (pig % gs)) * BM;
    int n0 = (pig / gs) * BN;

    // prologue: fill stages 0..2
    fill_stage(sb + 0 * STAGEB, 0 * BK, m0, n0); CP_COMMIT();
    fill_stage(sb + 1 * STAGEB, 1 * BK, m0, n0); CP_COMMIT();
    fill_stage(sb + 2 * STAGEB, 2 * BK, m0, n0); CP_COMMIT();

    float acc[2][8][4];
#pragma unroll
    for (int f = 0; f < 2; f++)
#pragma unroll
        for (int n = 0; n < 8; n++)
#pragma unroll
            for (int v = 0; v < 4; v++) acc[f][n][v] = 0.0f;

    const int g = lane >> 3, lr = lane & 7;

    for (int s = 0; s < NITER; s++) {
        CP_WAIT(2);
        __syncthreads();

        if (s + 3 < NITER) {
            fill_stage(sb + ((s + 3) & 3) * STAGEB, (s + 3) * BK, m0, n0);
            CP_COMMIT();
        }

        uint32_t st = sb + (s & 3) * STAGEB;
#pragma unroll
        for (int kk = 0; kk < 2; kk++) {
            // A fragments: matrices (r0-7,kLo),(r8-15,kLo),(r0-7,kHi),(r8-15,kHi)
            uint32_t ah[2][4], al[2][4];
#pragma unroll
            for (int f = 0; f < 2; f++) {
                uint32_t row = wm * 32 + f * 16 + lr + (g & 1) * 8;
                uint32_t c16 = kk * 2 + (g >> 1);
                uint32_t off = sw_off(row, c16);
                ldsm4(ah[f][0], ah[f][1], ah[f][2], ah[f][3], st + 0 * TILEB + off);
                ldsm4(al[f][0], al[f][1], al[f][2], al[f][3], st + 1 * TILEB + off);
            }
            // B fragments: [n][k] memory = col-major B -> non-trans ldmatrix
            uint32_t bh[8][2], bl[8][2];
#pragma unroll
            for (int p = 0; p < 4; p++) {
                uint32_t row = wn * 64 + p * 16 + lr + (g & 1) * 8;
                uint32_t c16 = kk * 2 + (g >> 1);
                uint32_t off = sw_off(row, c16);
                uint32_t r0, r1, r2, r3;
                ldsm4(r0, r1, r2, r3, st + 2 * TILEB + off);
                bh[p * 2 + 0][0] = r0; bh[p * 2 + 0][1] = r2;
                bh[p * 2 + 1][0] = r1; bh[p * 2 + 1][1] = r3;
                ldsm4(r0, r1, r2, r3, st + 3 * TILEB + off);
                bl[p * 2 + 0][0] = r0; bl[p * 2 + 0][1] = r2;
                bl[p * 2 + 1][0] = r1; bl[p * 2 + 1][1] = r3;
            }
#pragma unroll
            for (int f = 0; f < 2; f++)
#pragma unroll
                for (int n = 0; n < 8; n++) {
                    mma16816(acc[f][n], ah[f], bh[n]);
                    mma16816(acc[f][n], al[f], bh[n]);
                    mma16816(acc[f][n], ah[f], bl[n]);
                }
        }
    }

    // epilogue: accum -> g_G
#pragma unroll
    for (int f = 0; f < 2; f++) {
        int rbase = m0 + wm * 32 + f * 16 + (lane >> 2);
#pragma unroll
        for (int n = 0; n < 8; n++) {
            int col = n0 + wn * 64 + n * 8 + (lane & 3) * 2;
            float2 v0 = make_float2(acc[f][n][0], acc[f][n][1]);
            float2 v1 = make_float2(acc[f][n][2], acc[f][n][3]);
            *reinterpret_cast<float2*>(&g_G[(size_t)rbase * NDIM + col]) = v0;
            *reinterpret_cast<float2*>(&g_G[(size_t)(rbase + 8) * NDIM + col]) = v1;
        }
    }
}

// -------------------- elementwise cell epilogue ------------------------------
__device__ __forceinline__ float cell1(float gi, float gf, float go, float gc,
                                       float cv, float mv, float nv,
                                       float& c_new, float& m_new, float& n_new) {
    m_new = fmaxf(gf + mv, gi);
    float i_p = expf(gi - m_new);
    float f_p = expf(gf);                 // faithful: +m_new - m_new cancels
    float o_t = 1.0f / (1.0f + expf(-go));
    float z_t = tanhf(gc);
    c_new = f_p * cv + i_p * z_t;
    n_new = f_p * nv + i_p;
    return o_t * (c_new / n_new);
}

__global__ void __launch_bounds__(256) slstm_cell(
    const float* __restrict__ c, const float* __restrict__ m, const float* __restrict__ n,
    const float* __restrict__ bi, const float* __restrict__ bf, const float* __restrict__ bo,
    const float* __restrict__ bc, float* __restrict__ out) {
    size_t idx = (size_t)blockIdx.x * 256 + threadIdx.x;   // float4 index
    const size_t BD4 = (size_t)BDIM * DDIM / 4;
    size_t b = idx >> 10;
    size_t d4 = idx & 1023;
    const float4* G4 = reinterpret_cast<const float4*>(g_G);
    size_t rowbase = b * (NDIM / 4);
    float4 gi4 = G4[rowbase + 0 * 1024 + d4];
    float4 gf4 = G4[rowbase + 1 * 1024 + d4];
    float4 go4 = G4[rowbase + 2 * 1024 + d4];
    float4 gc4 = G4[rowbase + 3 * 1024 + d4];
    int d = (int)(d4 * 4);
    float4 bi4 = *reinterpret_cast<const float4*>(bi + d);
    float4 bf4 = *reinterpret_cast<const float4*>(bf + d);
    float4 bo4 = *reinterpret_cast<const float4*>(bo + d);
    float4 bc4 = *reinterpret_cast<const float4*>(bc + d);
    float4 c4 = reinterpret_cast<const float4*>(c)[idx];
    float4 m4 = reinterpret_cast<const float4*>(m)[idx];
    float4 n4 = reinterpret_cast<const float4*>(n)[idx];

    float4 h4, cn4, mn4, nn4;
    h4.x = cell1(gi4.x + bi4.x, gf4.x + bf4.x, go4.x + bo4.x, gc4.x + bc4.x, c4.x, m4.x, n4.x, cn4.x, mn4.x, nn4.x);
    h4.y = cell1(gi4.y + bi4.y, gf4.y + bf4.y, go4.y + bo4.y, gc4.y + bc4.y, c4.y, m4.y, n4.y, cn4.y, mn4.y, nn4.y);
    h4.z = cell1(gi4.z + bi4.z, gf4.z + bf4.z, go4.z + bo4.z, gc4.z + bc4.z, c4.z, m4.z, n4.z, cn4.z, mn4.z, nn4.z);
    h4.w = cell1(gi4.w + bi4.w, gf4.w + bf4.w, go4.w + bo4.w, gc4.w + bc4.w, c4.w, m4.w, n4.w, cn4.w, mn4.w, nn4.w);

    float4* o4 = reinterpret_cast<float4*>(out);
    o4[0 * BD4 + idx] = h4;
    o4[1 * BD4 + idx] = cn4;
    o4[2 * BD4 + idx] = mn4;
    o4[3 * BD4 + idx] = nn4;
}

// -------------------- launcher ----------------------------------------------
extern "C" void kernel_launch(void* const* d_in, const int* in_sizes, int n_in,
                              void* d_out, int out_size) {
    (void)in_sizes; (void)n_in; (void)out_size;
    const float* x  = (const float*)d_in[0];
    const float* h  = (const float*)d_in[1];
    const float* c  = (const float*)d_in[2];
    const float* m  = (const float*)d_in[3];
    const float* n  = (const float*)d_in[4];
    const float* wi = (const float*)d_in[5];
    const float* wf = (const float*)d_in[6];
    const float* wo = (const float*)d_in[7];
    const float* wc = (const float*)d_in[8];
    const float* ui = (const float*)d_in[9];
    const float* uf = (const float*)d_in[10];
    const float* uo = (const float*)d_in[11];
    const float* uc = (const float*)d_in[12];
    const float* bi = (const float*)d_in[13];
    const float* bf = (const float*)d_in[14];
    const float* bo = (const float*)d_in[15];
    const float* bc = (const float*)d_in[16];

    cudaFuncSetAttribute(slstm_gemm, cudaFuncAttributeMaxDynamicSharedMemorySize, SMEMB);

    prep_x<<<65536, 256>>>(x);
    prep_h<<<dim3(128, 128), dim3(32, 8)>>>(h);
    prep_w<<<dim3(128, 128, 8), dim3(32, 8)>>>(wi, wf, wo, wc, ui, uf, uo, uc);
    slstm_gemm<<<4096, 256, SMEMB>>>();
    slstm_cell<<<16384, 256>>>(c, m, n, bi, bf, bo, bc, (float*)d_out);
}

// round 3
// speedup vs baseline: 1.5460x; 1.5460x over previous
#include <cuda_runtime.h>
#include <cuda_fp16.h>
#include <cstdint>

// ============================================================================
// sLSTM cell, B=4096, D=4096 on sm_103a (legacy mma path; tcgen05 PTX not
// accepted by the harness's compute_103 virtual-arch compile).
// G = [x | h^T] (4096 x 8192) @ Wcat (8192 x 16384), gates [i,f,o,c] along N.
// fp16 2-term split on A only: G = Ahi*Bhi + Alo*Bhi  (fp32 accum).
//   dropped term A*(B - fl16(B)) -> gate abs err ~4e-4  (< 1e-3 budget)
// GEMM: cp.async 4-stage pipeline + ldmatrix + mma.sync.m16n8k16.f16,
//       24KB/stage -> 96KB/CTA -> 2 CTAs/SM for latency hiding.
// ============================================================================

#define BDIM 4096
#define DDIM 4096
#define KDIM 8192
#define NDIM 16384

#define BM 128
#define BN 128
#define BK 32
#define STAGES 4
#define NITER (KDIM / BK)          // 256
#define TILEB (BM * BK * 2)        // 8192 bytes per operand tile
#define STAGEB (3 * TILEB)         // 24576 (Ahi,Alo,Bhi)
#define SMEMB (STAGES * STAGEB)    // 98304

// -------------------- scratch (module-scope, allowed) -----------------------
__device__ __align__(256) __half g_Ahi[(size_t)BDIM * KDIM];
__device__ __align__(256) __half g_Alo[(size_t)BDIM * KDIM];
__device__ __align__(256) __half g_Bhi[(size_t)NDIM * KDIM];
__device__ __align__(256) float  g_G  [(size_t)BDIM * NDIM];

// -------------------- PTX helpers -------------------------------------------
__device__ __forceinline__ uint32_t smem_u32(const void* p) {
    uint32_t a;
    asm("{ .reg .u64 t; cvta.to.shared.u64 t, %1; cvt.u32.u64 %0, t; }"
        : "=r"(a) : "l"(p));
    return a;
}
__device__ __forceinline__ void cp_async16(uint32_t dst, const void* src) {
    asm volatile("cp.async.cg.shared.global [%0], [%1], 16;" :: "r"(dst), "l"(src) : "memory");
}
#define CP_COMMIT() asm volatile("cp.async.commit_group;" ::: "memory")
#define CP_WAIT(N)  asm volatile("cp.async.wait_group %0;" :: "n"(N) : "memory")

__device__ __forceinline__ void ldsm4(uint32_t& r0, uint32_t& r1, uint32_t& r2, uint32_t& r3,
                                      uint32_t addr) {
    asm volatile("ldmatrix.sync.aligned.m8n8.x4.shared.b16 {%0,%1,%2,%3}, [%4];"
                 : "=r"(r0), "=r"(r1), "=r"(r2), "=r"(r3) : "r"(addr));
}
__device__ __forceinline__ void mma16816(float* c, const uint32_t* a, const uint32_t* b) {
    asm volatile(
        "mma.sync.aligned.m16n8k16.row.col.f32.f16.f16.f32 "
        "{%0,%1,%2,%3}, {%4,%5,%6,%7}, {%8,%9}, {%0,%1,%2,%3};"
        : "+f"(c[0]), "+f"(c[1]), "+f"(c[2]), "+f"(c[3])
        : "r"(a[0]), "r"(a[1]), "r"(a[2]), "r"(a[3]), "r"(b[0]), "r"(b[1]));
}

// swizzled byte offset within one [128][BK] fp16 tile (64B rows).
// conflict-free for the cp.async writes and the ldmatrix 8-row reads.
__device__ __forceinline__ uint32_t sw_off(uint32_t row, uint32_t c16) {
    return row * 64u + ((c16 ^ ((row >> 1) & 3u)) << 4);
}

// -------------------- prep kernels ------------------------------------------
__device__ __forceinline__ void split_storeA(float v, size_t o) {
    __half hi = __float2half_rn(v);
    g_Ahi[o] = hi;
    g_Alo[o] = __float2half_rn(v - __half2float(hi));
}

__global__ void __launch_bounds__(256) prep_x(const float* __restrict__ x) {
    size_t i = (size_t)blockIdx.x * 256 + threadIdx.x;   // 16,777,216
    int b = (int)(i >> 12), k = (int)(i & 4095);
    split_storeA(x[i], (size_t)b * KDIM + k);
}

__global__ void __launch_bounds__(256) prep_h(const float* __restrict__ h) {
    __shared__ float t[32][33];
    int tx = threadIdx.x, ty = threadIdx.y;
    int b0 = blockIdx.x * 32, r0 = blockIdx.y * 32;
#pragma unroll
    for (int i = 0; i < 4; i++)
        t[ty + 8 * i][tx] = h[(size_t)(r0 + ty + 8 * i) * DDIM + b0 + tx];
    __syncthreads();
#pragma unroll
    for (int i = 0; i < 4; i++) {
        size_t o = (size_t)(b0 + ty + 8 * i) * KDIM + 4096 + r0 + tx;
        split_storeA(t[tx][ty + 8 * i], o);
    }
}

__global__ void __launch_bounds__(256) prep_w(
    const float* w0, const float* w1, const float* w2, const float* w3,
    const float* u0, const float* u1, const float* u2, const float* u3) {
    __shared__ float t[32][33];
    int tx = threadIdx.x, ty = threadIdx.y;
    int z = blockIdx.z;
    const float* arr[8] = {w0, w1, w2, w3, u0, u1, u2, u3};
    const float* src = arr[z];
    int gate = z & 3, half2_ = z >> 2;
    int d0 = blockIdx.x * 32, k0 = blockIdx.y * 32;
#pragma unroll
    for (int i = 0; i < 4; i++)
        t[ty + 8 * i][tx] = src[(size_t)(k0 + ty + 8 * i) * DDIM + d0 + tx];
    __syncthreads();
#pragma unroll
    for (int i = 0; i < 4; i++) {
        float v = t[tx][ty + 8 * i];
        size_t o = (size_t)(gate * 4096 + d0 + ty + 8 * i) * KDIM + half2_ * 4096 + k0 + tx;
        g_Bhi[o] = __float2half_rn(v);
    }
}

// -------------------- GEMM kernel -------------------------------------------
__device__ __forceinline__ void fill_stage(uint32_t sbase, int kblk, int m0, int n0) {
    const int tid = threadIdx.x;
#pragma unroll
    for (int j = 0; j < 2; j++) {
        int q = tid + 256 * j;          // 16B chunk id, 0..511
        int row = q >> 2;               // 0..127
        int c = q & 3;                  // 16B chunk within 64B row
        uint32_t off = sw_off(row, c);
        size_t ka = (size_t)(m0 + row) * KDIM + kblk + c * 8;
        size_t kb = (size_t)(n0 + row) * KDIM + kblk + c * 8;
        cp_async16(sbase + 0 * TILEB + off, &g_Ahi[ka]);
        cp_async16(sbase + 1 * TILEB + off, &g_Alo[ka]);
        cp_async16(sbase + 2 * TILEB + off, &g_Bhi[kb]);
    }
}

__global__ void __launch_bounds__(256, 2) slstm_gemm() {
    extern __shared__ char smem[];
    uint32_t sb = smem_u32(smem);
    const int tid = threadIdx.x;
    const int wid = tid >> 5;
    const int lane = tid & 31;
    const int wm = wid >> 1;            // 0..3  (M warp, 32 rows)
    const int wn = wid & 1;             // 0..1  (N warp, 64 cols)

    // supertile rasterization for L2 reuse
    const int grid_m = BDIM / BM, grid_n = NDIM / BN;   // 32, 128
    const int GROUP = 8;
    int pid = blockIdx.x;
    int npg = GROUP * grid_n;
    int first_m = (pid / npg) * GROUP;
    int gs = min(grid_m - first_m, GROUP);
    int pig = pid % npg;
    int m0 = (first_m + (pig % gs)) * BM;
    int n0 = (pig / gs) * BN;

    // prologue: fill stages 0..2
    fill_stage(sb + 0 * STAGEB, 0 * BK, m0, n0); CP_COMMIT();
    fill_stage(sb + 1 * STAGEB, 1 * BK, m0, n0); CP_COMMIT();
    fill_stage(sb + 2 * STAGEB, 2 * BK, m0, n0); CP_COMMIT();

    float acc[2][8][4];
#pragma unroll
    for (int f = 0; f < 2; f++)
#pragma unroll
        for (int n = 0; n < 8; n++)
#pragma unroll
            for (int v = 0; v < 4; v++) acc[f][n][v] = 0.0f;

    const int g = lane >> 3, lr = lane & 7;

    for (int s = 0; s < NITER; s++) {
        CP_WAIT(2);
        __syncthreads();

        if (s + 3 < NITER) {
            fill_stage(sb + ((s + 3) & 3) * STAGEB, (s + 3) * BK, m0, n0);
            CP_COMMIT();
        }

        uint32_t st = sb + (s & 3) * STAGEB;
#pragma unroll
        for (int kk = 0; kk < 2; kk++) {
            // A fragments
            uint32_t ah[2][4], al[2][4];
#pragma unroll
            for (int f = 0; f < 2; f++) {
                uint32_t row = wm * 32 + f * 16 + lr + (g & 1) * 8;
                uint32_t c16 = kk * 2 + (g >> 1);
                uint32_t off = sw_off(row, c16);
                ldsm4(ah[f][0], ah[f][1], ah[f][2], ah[f][3], st + 0 * TILEB + off);
                ldsm4(al[f][0], al[f][1], al[f][2], al[f][3], st + 1 * TILEB + off);
            }
            // B fragments: [n][k] memory = col-major B -> non-trans ldmatrix
            uint32_t bh[8][2];
#pragma unroll
            for (int p = 0; p < 4; p++) {
                uint32_t row = wn * 64 + p * 16 + lr + (g & 1) * 8;
                uint32_t c16 = kk * 2 + (g >> 1);
                uint32_t off = sw_off(row, c16);
                uint32_t r0, r1, r2, r3;
                ldsm4(r0, r1, r2, r3, st + 2 * TILEB + off);
                bh[p * 2 + 0][0] = r0; bh[p * 2 + 0][1] = r2;
                bh[p * 2 + 1][0] = r1; bh[p * 2 + 1][1] = r3;
            }
#pragma unroll
            for (int f = 0; f < 2; f++)
#pragma unroll
                for (int n = 0; n < 8; n++) {
                    mma16816(acc[f][n], ah[f], bh[n]);
                    mma16816(acc[f][n], al[f], bh[n]);
                }
        }
    }

    // epilogue: accum -> g_G
#pragma unroll
    for (int f = 0; f < 2; f++) {
        int rbase = m0 + wm * 32 + f * 16 + (lane >> 2);
#pragma unroll
        for (int n = 0; n < 8; n++) {
            int col = n0 + wn * 64 + n * 8 + (lane & 3) * 2;
            float2 v0 = make_float2(acc[f][n][0], acc[f][n][1]);
            float2 v1 = make_float2(acc[f][n][2], acc[f][n][3]);
            *reinterpret_cast<float2*>(&g_G[(size_t)rbase * NDIM + col]) = v0;
            *reinterpret_cast<float2*>(&g_G[(size_t)(rbase + 8) * NDIM + col]) = v1;
        }
    }
}

// -------------------- elementwise cell epilogue ------------------------------
__device__ __forceinline__ float cell1(float gi, float gf, float go, float gc,
                                       float cv, float mv, float nv,
                                       float& c_new, float& m_new, float& n_new) {
    m_new = fmaxf(gf + mv, gi);
    float i_p = expf(gi - m_new);
    float f_p = expf(gf);                 // faithful: +m_new - m_new cancels
    float o_t = 1.0f / (1.0f + expf(-go));
    float z_t = tanhf(gc);
    c_new = f_p * cv + i_p * z_t;
    n_new = f_p * nv + i_p;
    return o_t * (c_new / n_new);
}

__global__ void __launch_bounds__(256) slstm_cell(
    const float* __restrict__ c, const float* __restrict__ m, const float* __restrict__ n,
    const float* __restrict__ bi, const float* __restrict__ bf, const float* __restrict__ bo,
    const float* __restrict__ bc, float* __restrict__ out) {
    size_t idx = (size_t)blockIdx.x * 256 + threadIdx.x;   // float4 index
    const size_t BD4 = (size_t)BDIM * DDIM / 4;
    size_t b = idx >> 10;
    size_t d4 = idx & 1023;
    const float4* G4 = reinterpret_cast<const float4*>(g_G);
    size_t rowbase = b * (NDIM / 4);
    float4 gi4 = G4[rowbase + 0 * 1024 + d4];
    float4 gf4 = G4[rowbase + 1 * 1024 + d4];
    float4 go4 = G4[rowbase + 2 * 1024 + d4];
    float4 gc4 = G4[rowbase + 3 * 1024 + d4];
    int d = (int)(d4 * 4);
    float4 bi4 = *reinterpret_cast<const float4*>(bi + d);
    float4 bf4 = *reinterpret_cast<const float4*>(bf + d);
    float4 bo4 = *reinterpret_cast<const float4*>(bo + d);
    float4 bc4 = *reinterpret_cast<const float4*>(bc + d);
    float4 c4 = reinterpret_cast<const float4*>(c)[idx];
    float4 m4 = reinterpret_cast<const float4*>(m)[idx];
    float4 n4 = reinterpret_cast<const float4*>(n)[idx];

    float4 h4, cn4, mn4, nn4;
    h4.x = cell1(gi4.x + bi4.x, gf4.x + bf4.x, go4.x + bo4.x, gc4.x + bc4.x, c4.x, m4.x, n4.x, cn4.x, mn4.x, nn4.x);
    h4.y = cell1(gi4.y + bi4.y, gf4.y + bf4.y, go4.y + bo4.y, gc4.y + bc4.y, c4.y, m4.y, n4.y, cn4.y, mn4.y, nn4.y);
    h4.z = cell1(gi4.z + bi4.z, gf4.z + bf4.z, go4.z + bo4.z, gc4.z + bc4.z, c4.z, m4.z, n4.z, cn4.z, mn4.z, nn4.z);
    h4.w = cell1(gi4.w + bi4.w, gf4.w + bf4.w, go4.w + bo4.w, gc4.w + bc4.w, c4.w, m4.w, n4.w, cn4.w, mn4.w, nn4.w);

    float4* o4 = reinterpret_cast<float4*>(out);
    o4[0 * BD4 + idx] = h4;
    o4[1 * BD4 + idx] = cn4;
    o4[2 * BD4 + idx] = mn4;
    o4[3 * BD4 + idx] = nn4;
}

// -------------------- launcher ----------------------------------------------
extern "C" void kernel_launch(void* const* d_in, const int* in_sizes, int n_in,
                              void* d_out, int out_size) {
    (void)in_sizes; (void)n_in; (void)out_size;
    const float* x  = (const float*)d_in[0];
    const float* h  = (const float*)d_in[1];
    const float* c  = (const float*)d_in[2];
    const float* m  = (const float*)d_in[3];
    const float* n  = (const float*)d_in[4];
    const float* wi = (const float*)d_in[5];
    const float* wf = (const float*)d_in[6];
    const float* wo = (const float*)d_in[7];
    const float* wc = (const float*)d_in[8];
    const float* ui = (const float*)d_in[9];
    const float* uf = (const float*)d_in[10];
    const float* uo = (const float*)d_in[11];
    const float* uc = (const float*)d_in[12];
    const float* bi = (const float*)d_in[13];
    const float* bf = (const float*)d_in[14];
    const float* bo = (const float*)d_in[15];
    const float* bc = (const float*)d_in[16];

    cudaFuncSetAttribute(slstm_gemm, cudaFuncAttributeMaxDynamicSharedMemorySize, SMEMB);

    prep_x<<<65536, 256>>>(x);
    prep_h<<<dim3(128, 128), dim3(32, 8)>>>(h);
    prep_w<<<dim3(128, 128, 8), dim3(32, 8)>>>(wi, wf, wo, wc, ui, uf, uo, uc);
    slstm_gemm<<<4096, 256, SMEMB>>>();
    slstm_cell<<<16384, 256>>>(c, m, n, bi, bf, bo, bc, (float*)d_out);
}

// round 5
// speedup vs baseline: 3.1671x; 2.0486x over previous
#include <cuda_runtime.h>
#include <cuda_fp16.h>
#include <cstdint>

// ============================================================================
// sLSTM cell, B=4096, D=4096 on sm_103a (legacy mma path; tcgen05 PTX not
// accepted through the harness's compute_103 virtual-arch compile).
// G = [x | h^T] (4096 x 8192) @ Wcat (8192 x 16384), gates [i,f,o,c] along N.
// SINGLE fp16 pass (fp32 accum); calibrated error model predicts ~4.2e-4.
// GEMM: cp.async 4-stage pipeline + ldmatrix + mma.sync.m16n8k16.f16.
// Addresses hoisted with pure ADDs (no XOR base-bit assumptions);
// pipeline tail drained with CP_WAIT(2,2,1,0).
// ============================================================================

#define BDIM 4096
#define DDIM 4096
#define KDIM 8192
#define NDIM 16384

#define BM 128
#define BN 128
#define BK 32
#define STAGES 4
#define NITER (KDIM / BK)          // 256
#define TILEB (BM * BK * 2)        // 8192 bytes per operand tile
#define STAGEB (2 * TILEB)         // 16384 (A, B)
#define SMEMB (STAGES * STAGEB)    // 65536

// -------------------- scratch (module-scope, allowed) -----------------------
__device__ __align__(256) __half g_A[(size_t)BDIM * KDIM];
__device__ __align__(256) __half g_B[(size_t)NDIM * KDIM];
__device__ __align__(256) float  g_G[(size_t)BDIM * NDIM];

// -------------------- PTX helpers -------------------------------------------
__device__ __forceinline__ uint32_t smem_u32(const void* p) {
    uint32_t a;
    asm("{ .reg .u64 t; cvta.to.shared.u64 t, %1; cvt.u32.u64 %0, t; }"
        : "=r"(a) : "l"(p));
    return a;
}
__device__ __forceinline__ void cp_async16(uint32_t dst, const void* src) {
    asm volatile("cp.async.cg.shared.global [%0], [%1], 16;" :: "r"(dst), "l"(src) : "memory");
}
#define CP_COMMIT() asm volatile("cp.async.commit_group;" ::: "memory")
#define CP_WAIT(N)  asm volatile("cp.async.wait_group %0;" :: "n"(N) : "memory")

__device__ __forceinline__ void ldsm4(uint32_t& r0, uint32_t& r1, uint32_t& r2, uint32_t& r3,
                                      uint32_t addr) {
    asm volatile("ldmatrix.sync.aligned.m8n8.x4.shared.b16 {%0,%1,%2,%3}, [%4];"
                 : "=r"(r0), "=r"(r1), "=r"(r2), "=r"(r3) : "r"(addr));
}
__device__ __forceinline__ void mma16816(float* c, const uint32_t* a, const uint32_t* b) {
    asm volatile(
        "mma.sync.aligned.m16n8k16.row.col.f32.f16.f16.f32 "
        "{%0,%1,%2,%3}, {%4,%5,%6,%7}, {%8,%9}, {%0,%1,%2,%3};"
        : "+f"(c[0]), "+f"(c[1]), "+f"(c[2]), "+f"(c[3])
        : "r"(a[0]), "r"(a[1]), "r"(a[2]), "r"(a[3]), "r"(b[0]), "r"(b[1]));
}

// swizzled byte offset within one [128][BK] fp16 tile (64B rows).
// conflict-free for the cp.async writes and the ldmatrix 8-row reads.
__device__ __forceinline__ uint32_t sw_off(uint32_t row, uint32_t c16) {
    return row * 64u + ((c16 ^ ((row >> 1) & 3u)) << 4);
}

// -------------------- prep kernels ------------------------------------------
__global__ void __launch_bounds__(256) prep_x(const float* __restrict__ x) {
    size_t i = (size_t)blockIdx.x * 256 + threadIdx.x;   // 16,777,216
    int b = (int)(i >> 12), k = (int)(i & 4095);
    g_A[(size_t)b * KDIM + k] = __float2half_rn(x[i]);
}

__global__ void __launch_bounds__(256) prep_h(const float* __restrict__ h) {
    __shared__ float t[32][33];
    int tx = threadIdx.x, ty = threadIdx.y;
    int b0 = blockIdx.x * 32, r0 = blockIdx.y * 32;
#pragma unroll
    for (int i = 0; i < 4; i++)
        t[ty + 8 * i][tx] = h[(size_t)(r0 + ty + 8 * i) * DDIM + b0 + tx];
    __syncthreads();
#pragma unroll
    for (int i = 0; i < 4; i++) {
        size_t o = (size_t)(b0 + ty + 8 * i) * KDIM + 4096 + r0 + tx;
        g_A[o] = __float2half_rn(t[tx][ty + 8 * i]);
    }
}

__global__ void __launch_bounds__(256) prep_w(
    const float* w0, const float* w1, const float* w2, const float* w3,
    const float* u0, const float* u1, const float* u2, const float* u3) {
    __shared__ float t[32][33];
    int tx = threadIdx.x, ty = threadIdx.y;
    int z = blockIdx.z;
    const float* arr[8] = {w0, w1, w2, w3, u0, u1, u2, u3};
    const float* src = arr[z];
    int gate = z & 3, khalf = z >> 2;
    int d0 = blockIdx.x * 32, k0 = blockIdx.y * 32;
#pragma unroll
    for (int i = 0; i < 4; i++)
        t[ty + 8 * i][tx] = src[(size_t)(k0 + ty + 8 * i) * DDIM + d0 + tx];
    __syncthreads();
#pragma unroll
    for (int i = 0; i < 4; i++) {
        size_t o = (size_t)(gate * 4096 + d0 + ty + 8 * i) * KDIM + khalf * 4096 + k0 + tx;
        g_B[o] = __float2half_rn(t[tx][ty + 8 * i]);
    }
}

// -------------------- GEMM kernel -------------------------------------------
__device__ __forceinline__ void fill_stage(uint32_t sbase, int kblk, int m0, int n0) {
    const int tid = threadIdx.x;
#pragma unroll
    for (int j = 0; j < 2; j++) {
        int q = tid + 256 * j;          // 16B chunk id, 0..511
        int row = q >> 2;               // 0..127
        int c = q & 3;                  // 16B chunk within 64B row
        uint32_t off = sw_off(row, c);
        size_t ka = (size_t)(m0 + row) * KDIM + kblk + c * 8;
        size_t kb = (size_t)(n0 + row) * KDIM + kblk + c * 8;
        cp_async16(sbase + 0 * TILEB + off, &g_A[ka]);
        cp_async16(sbase + 1 * TILEB + off, &g_B[kb]);
    }
}

// one pipeline step: wait, sync, optional refill of slot (U+3)&3, MMA slot U.
template<int U, int WAITN>
__device__ __forceinline__ void gemm_step(
    bool dofill, int s, uint32_t sb, int m0, int n0,
    const uint32_t (&aA)[2][2], const uint32_t (&aB)[4][2], float (&acc)[2][8][4]) {
    CP_WAIT(WAITN);
    __syncthreads();
    if (dofill) {
        fill_stage(sb + ((U + 3) & 3) * STAGEB, (s + 3) * BK, m0, n0);
        CP_COMMIT();
    }
#pragma unroll
    for (int kk = 0; kk < 2; kk++) {
        uint32_t a[2][4];
#pragma unroll
        for (int f = 0; f < 2; f++)
            ldsm4(a[f][0], a[f][1], a[f][2], a[f][3], aA[f][kk] + U * STAGEB);
        uint32_t b[8][2];
#pragma unroll
        for (int p = 0; p < 4; p++) {
            uint32_t r0, r1, r2, r3;
            ldsm4(r0, r1, r2, r3, aB[p][kk] + U * STAGEB);
            b[p * 2 + 0][0] = r0; b[p * 2 + 0][1] = r2;
            b[p * 2 + 1][0] = r1; b[p * 2 + 1][1] = r3;
        }
#pragma unroll
        for (int f = 0; f < 2; f++)
#pragma unroll
            for (int n = 0; n < 8; n++)
                mma16816(acc[f][n], a[f], b[n]);
    }
}

__global__ void __launch_bounds__(256, 2) slstm_gemm() {
    extern __shared__ char smem[];
    uint32_t sb = smem_u32(smem);
    const int tid = threadIdx.x;
    const int wid = tid >> 5;
    const int lane = tid & 31;
    const int wm = wid >> 1;            // 0..3  (M warp, 32 rows)
    const int wn = wid & 1;             // 0..1  (N warp, 64 cols)

    // supertile rasterization for L2 reuse
    const int grid_m = BDIM / BM, grid_n = NDIM / BN;   // 32, 128
    const int GROUP = 8;
    int pid = blockIdx.x;
    int npg = GROUP * grid_n;
    int first_m = (pid / npg) * GROUP;
    int gs = min(grid_m - first_m, GROUP);
    int pig = pid % npg;
    int m0 = (first_m + (pig % gs)) * BM;
    int n0 = (pig / gs) * BN;

    // prologue: fill stages 0..2
    fill_stage(sb + 0 * STAGEB, 0 * BK, m0, n0); CP_COMMIT();
    fill_stage(sb + 1 * STAGEB, 1 * BK, m0, n0); CP_COMMIT();
    fill_stage(sb + 2 * STAGEB, 2 * BK, m0, n0); CP_COMMIT();

    float acc[2][8][4];
#pragma unroll
    for (int f = 0; f < 2; f++)
#pragma unroll
        for (int n = 0; n < 8; n++)
#pragma unroll
            for (int v = 0; v < 4; v++) acc[f][n][v] = 0.0f;

    const int g = lane >> 3, lr = lane & 7;

    // hoisted swizzled ldmatrix addresses for stage slot 0, kk = 0/1.
    // slot U adds the compile-time immediate U*STAGEB (pure ADD, base-safe).
    uint32_t aA[2][2], aB[4][2];
#pragma unroll
    for (int f = 0; f < 2; f++)
#pragma unroll
        for (int kk = 0; kk < 2; kk++)
            aA[f][kk] = sb + 0 * TILEB +
                        sw_off(wm * 32 + f * 16 + lr + (g & 1) * 8, kk * 2 + (g >> 1));
#pragma unroll
    for (int p = 0; p < 4; p++)
#pragma unroll
        for (int kk = 0; kk < 2; kk++)
            aB[p][kk] = sb + 1 * TILEB +
                        sw_off(wn * 64 + p * 16 + lr + (g & 1) * 8, kk * 2 + (g >> 1));

    // main loop: stages 0..251 (all refill; wait(2) is exact)
    for (int s4 = 0; s4 < NITER - 4; s4 += 4) {
        gemm_step<0, 2>(true, s4 + 0, sb, m0, n0, aA, aB, acc);
        gemm_step<1, 2>(true, s4 + 1, sb, m0, n0, aA, aB, acc);
        gemm_step<2, 2>(true, s4 + 2, sb, m0, n0, aA, aB, acc);
        gemm_step<3, 2>(true, s4 + 3, sb, m0, n0, aA, aB, acc);
    }
    // tail: stages 252..255 with exact drain waits
    gemm_step<0, 2>(true,  NITER - 4, sb, m0, n0, aA, aB, acc);   // fills stage 255
    gemm_step<1, 2>(false, NITER - 3, sb, m0, n0, aA, aB, acc);
    gemm_step<2, 1>(false, NITER - 2, sb, m0, n0, aA, aB, acc);
    gemm_step<3, 0>(false, NITER - 1, sb, m0, n0, aA, aB, acc);

    // epilogue: accum -> g_G
#pragma unroll
    for (int f = 0; f < 2; f++) {
        int rbase = m0 + wm * 32 + f * 16 + (lane >> 2);
#pragma unroll
        for (int n = 0; n < 8; n++) {
            int col = n0 + wn * 64 + n * 8 + (lane & 3) * 2;
            float2 v0 = make_float2(acc[f][n][0], acc[f][n][1]);
            float2 v1 = make_float2(acc[f][n][2], acc[f][n][3]);
            *reinterpret_cast<float2*>(&g_G[(size_t)rbase * NDIM + col]) = v0;
            *reinterpret_cast<float2*>(&g_G[(size_t)(rbase + 8) * NDIM + col]) = v1;
        }
    }
}

// -------------------- elementwise cell epilogue ------------------------------
__device__ __forceinline__ float cell1(float gi, float gf, float go, float gc,
                                       float cv, float mv, float nv,
                                       float& c_new, float& m_new, float& n_new) {
    m_new = fmaxf(gf + mv, gi);
    float i_p = expf(gi - m_new);
    float f_p = expf(gf);                 // faithful: +m_new - m_new cancels
    float o_t = 1.0f / (1.0f + expf(-go));
    float z_t = tanhf(gc);
    c_new = f_p * cv + i_p * z_t;
    n_new = f_p * nv + i_p;
    return o_t * (c_new / n_new);
}

__global__ void __launch_bounds__(256) slstm_cell(
    const float* __restrict__ c, const float* __restrict__ m, const float* __restrict__ n,
    const float* __restrict__ bi, const float* __restrict__ bf, const float* __restrict__ bo,
    const float* __restrict__ bc, float* __restrict__ out) {
    size_t idx = (size_t)blockIdx.x * 256 + threadIdx.x;   // float4 index
    const size_t BD4 = (size_t)BDIM * DDIM / 4;
    size_t b = idx >> 10;
    size_t d4 = idx & 1023;
    const float4* G4 = reinterpret_cast<const float4*>(g_G);
    size_t rowbase = b * (NDIM / 4);
    float4 gi4 = G4[rowbase + 0 * 1024 + d4];
    float4 gf4 = G4[rowbase + 1 * 1024 + d4];
    float4 go4 = G4[rowbase + 2 * 1024 + d4];
    float4 gc4 = G4[rowbase + 3 * 1024 + d4];
    int d = (int)(d4 * 4);
    float4 bi4 = *reinterpret_cast<const float4*>(bi + d);
    float4 bf4 = *reinterpret_cast<const float4*>(bf + d);
    float4 bo4 = *reinterpret_cast<const float4*>(bo + d);
    float4 bc4 = *reinterpret_cast<const float4*>(bc + d);
    float4 c4 = reinterpret_cast<const float4*>(c)[idx];
    float4 m4 = reinterpret_cast<const float4*>(m)[idx];
    float4 n4 = reinterpret_cast<const float4*>(n)[idx];

    float4 h4, cn4, mn4, nn4;
    h4.x = cell1(gi4.x + bi4.x, gf4.x + bf4.x, go4.x + bo4.x, gc4.x + bc4.x, c4.x, m4.x, n4.x, cn4.x, mn4.x, nn4.x);
    h4.y = cell1(gi4.y + bi4.y, gf4.y + bf4.y, go4.y + bo4.y, gc4.y + bc4.y, c4.y, m4.y, n4.y, cn4.y, mn4.y, nn4.y);
    h4.z = cell1(gi4.z + bi4.z, gf4.z + bf4.z, go4.z + bo4.z, gc4.z + bc4.z, c4.z, m4.z, n4.z, cn4.z, mn4.z, nn4.z);
    h4.w = cell1(gi4.w + bi4.w, gf4.w + bf4.w, go4.w + bo4.w, gc4.w + bc4.w, c4.w, m4.w, n4.w, cn4.w, mn4.w, nn4.w);

    float4* o4 = reinterpret_cast<float4*>(out);
    o4[0 * BD4 + idx] = h4;
    o4[1 * BD4 + idx] = cn4;
    o4[2 * BD4 + idx] = mn4;
    o4[3 * BD4 + idx] = nn4;
}

// -------------------- launcher ----------------------------------------------
extern "C" void kernel_launch(void* const* d_in, const int* in_sizes, int n_in,
                              void* d_out, int out_size) {
    (void)in_sizes; (void)n_in; (void)out_size;
    const float* x  = (const float*)d_in[0];
    const float* h  = (const float*)d_in[1];
    const float* c  = (const float*)d_in[2];
    const float* m  = (const float*)d_in[3];
    const float* n  = (const float*)d_in[4];
    const float* wi = (const float*)d_in[5];
    const float* wf = (const float*)d_in[6];
    const float* wo = (const float*)d_in[7];
    const float* wc = (const float*)d_in[8];
    const float* ui = (const float*)d_in[9];
    const float* uf = (const float*)d_in[10];
    const float* uo = (const float*)d_in[11];
    const float* uc = (const float*)d_in[12];
    const float* bi = (const float*)d_in[13];
    const float* bf = (const float*)d_in[14];
    const float* bo = (const float*)d_in[15];
    const float* bc = (const float*)d_in[16];

    cudaFuncSetAttribute(slstm_gemm, cudaFuncAttributeMaxDynamicSharedMemorySize, SMEMB);

    prep_x<<<65536, 256>>>(x);
    prep_h<<<dim3(128, 128), dim3(32, 8)>>>(h);
    prep_w<<<dim3(128, 128, 8), dim3(32, 8)>>>(wi, wf, wo, wc, ui, uf, uo, uc);
    slstm_gemm<<<4096, 256, SMEMB>>>();
    slstm_cell<<<16384, 256>>>(c, m, n, bi, bf, bo, bc, (float*)d_out);
}

// round 6
// speedup vs baseline: 3.5583x; 1.1235x over previous
#include <cuda_runtime.h>
#include <cuda_fp16.h>
#include <cstdint>

// ============================================================================
// sLSTM cell, B=4096, D=4096 on sm_103a (legacy mma path; tcgen05 PTX not
// accepted through the harness's compute_103 virtual-arch compile).
// G = [x | h^T] (4096 x 8192) @ Wcat (8192 x 16384), gates [i,f,o,c] along N.
// SINGLE fp16 pass (fp32 accum); calibrated error ~4.1e-4 < 1e-3.
// GEMM: BK=64, 3-stage cp.async pipeline + ldmatrix + mma.sync.m16n8k16.f16.
//   - fill side: immediate smem offsets + two advancing global pointers
//   - ldsm side: hoisted addresses; kk=2,3 via per-thread ADD delta (bit-6
//     flip of the swizzled offset; sign = lane&4; pure ADD, base-safe)
// ============================================================================

#define BDIM 4096
#define DDIM 4096
#define KDIM 8192
#define NDIM 16384

#define BM 128
#define BN 128
#define BK 64
#define NITER (KDIM / BK)          // 128
#define TILEB (BM * BK * 2)        // 16384 bytes per operand tile
#define STAGEB (2 * TILEB)         // 32768 (A, B)
#define SMEMB (3 * STAGEB)         // 98304 -> 2 CTAs/SM

// -------------------- scratch (module-scope, allowed) -----------------------
__device__ __align__(256) __half g_A[(size_t)BDIM * KDIM];
__device__ __align__(256) __half g_B[(size_t)NDIM * KDIM];
__device__ __align__(256) float  g_G[(size_t)BDIM * NDIM];

// -------------------- PTX helpers -------------------------------------------
__device__ __forceinline__ uint32_t smem_u32(const void* p) {
    uint32_t a;
    asm("{ .reg .u64 t; cvta.to.shared.u64 t, %1; cvt.u32.u64 %0, t; }"
        : "=r"(a) : "l"(p));
    return a;
}
__device__ __forceinline__ void cp_async16(uint32_t dst, const void* src) {
    asm volatile("cp.async.cg.shared.global [%0], [%1], 16;" :: "r"(dst), "l"(src) : "memory");
}
#define CP_COMMIT() asm volatile("cp.async.commit_group;" ::: "memory")
#define CP_WAIT(N)  asm volatile("cp.async.wait_group %0;" :: "n"(N) : "memory")

__device__ __forceinline__ void ldsm4(uint32_t& r0, uint32_t& r1, uint32_t& r2, uint32_t& r3,
                                      uint32_t addr) {
    asm volatile("ldmatrix.sync.aligned.m8n8.x4.shared.b16 {%0,%1,%2,%3}, [%4];"
                 : "=r"(r0), "=r"(r1), "=r"(r2), "=r"(r3) : "r"(addr));
}
__device__ __forceinline__ void mma16816(float* c, const uint32_t* a, const uint32_t* b) {
    asm volatile(
        "mma.sync.aligned.m16n8k16.row.col.f32.f16.f16.f32 "
        "{%0,%1,%2,%3}, {%4,%5,%6,%7}, {%8,%9}, {%0,%1,%2,%3};"
        : "+f"(c[0]), "+f"(c[1]), "+f"(c[2]), "+f"(c[3])
        : "r"(a[0]), "r"(a[1]), "r"(a[2]), "r"(a[3]), "r"(b[0]), "r"(b[1]));
}

// swizzled byte offset within one [128][64] fp16 tile (128B rows, 8 chunks).
// conflict-free for cp.async writes and ldmatrix 8-row reads.
__device__ __forceinline__ uint32_t sw_off(uint32_t row, uint32_t c16) {
    return row * 128u + (((c16 ^ row) & 7u) << 4);
}

// -------------------- prep kernels ------------------------------------------
__global__ void __launch_bounds__(256) prep_x(const float* __restrict__ x) {
    size_t gid = (size_t)blockIdx.x * 256 + threadIdx.x;   // 8,388,608 pairs
    size_t i2 = gid * 2;
    int b = (int)(i2 >> 12), k = (int)(i2 & 4095);
    float2 v = reinterpret_cast<const float2*>(x)[gid];
    *reinterpret_cast<__half2*>(&g_A[(size_t)b * KDIM + k]) = __floats2half2_rn(v.x, v.y);
}

__global__ void __launch_bounds__(256) prep_h(const float* __restrict__ h) {
    __shared__ float t[32][33];
    int tx = threadIdx.x, ty = threadIdx.y;
    int b0 = blockIdx.x * 32, r0 = blockIdx.y * 32;
#pragma unroll
    for (int i = 0; i < 4; i++)
        t[ty + 8 * i][tx] = h[(size_t)(r0 + ty + 8 * i) * DDIM + b0 + tx];
    __syncthreads();
#pragma unroll
    for (int i = 0; i < 4; i++) {
        size_t o = (size_t)(b0 + ty + 8 * i) * KDIM + 4096 + r0 + tx;
        g_A[o] = __float2half_rn(t[tx][ty + 8 * i]);
    }
}

// 64x64 tile transpose; writes are 128B-coalesced half2 rows.
__global__ void __launch_bounds__(256) prep_w(
    const float* w0, const float* w1, const float* w2, const float* w3,
    const float* u0, const float* u1, const float* u2, const float* u3) {
    __shared__ float t[64][65];
    const int l = threadIdx.x;
    int z = blockIdx.z;
    const float* arr[8] = {w0, w1, w2, w3, u0, u1, u2, u3};
    const float* src = arr[z];
    int gate = z & 3, khalf = z >> 2;
    int d0 = blockIdx.x * 64, k0 = blockIdx.y * 64;
#pragma unroll
    for (int it = 0; it < 4; it++) {
        int idx = l + 256 * it;            // 0..1023
        int row = idx >> 4;                // k row 0..63
        int c4 = idx & 15;                 // float4 col
        float4 v = *reinterpret_cast<const float4*>(&src[(size_t)(k0 + row) * DDIM + d0 + c4 * 4]);
        t[row][c4 * 4 + 0] = v.x;
        t[row][c4 * 4 + 1] = v.y;
        t[row][c4 * 4 + 2] = v.z;
        t[row][c4 * 4 + 3] = v.w;
    }
    __syncthreads();
#pragma unroll
    for (int it = 0; it < 8; it++) {
        int idx = l + 256 * it;            // 0..2047
        int drow = idx >> 5;               // d row 0..63
        int cp = idx & 31;                 // half2 col (k pair)
        __half2 v = __floats2half2_rn(t[2 * cp][drow], t[2 * cp + 1][drow]);
        size_t o = (size_t)(gate * 4096 + d0 + drow) * KDIM + khalf * 4096 + k0 + 2 * cp;
        *reinterpret_cast<__half2*>(&g_B[o]) = v;
    }
}

// -------------------- GEMM kernel -------------------------------------------
// fill one 32KB stage: 8 cp.async/thread, immediate offsets, pointers advance.
__device__ __forceinline__ void fill(uint32_t sdstA, uint32_t sdstB,
                                     const char*& pa, const char*& pb) {
    const size_t RSTEP = (size_t)32 * KDIM * 2;   // 32 rows in bytes
#pragma unroll
    for (int j = 0; j < 4; j++) {
        cp_async16(sdstA + 4096 * j, pa + (size_t)j * RSTEP);
        cp_async16(sdstB + 4096 * j, pb + (size_t)j * RSTEP);
    }
    pa += BK * 2;
    pb += BK * 2;
    CP_COMMIT();
}

// one pipeline step: wait, sync, optional refill of slot (U+2)%3, MMA slot U.
template<int U, int WAITN, bool FILL>
__device__ __forceinline__ void gstep(
    uint32_t sb, uint32_t offA, uint32_t offB,
    const char*& pa, const char*& pb,
    const uint32_t (&aA)[2][2], const uint32_t (&aB)[4][2], int dlt,
    float (&acc)[2][8][4]) {
    CP_WAIT(WAITN);
    __syncthreads();
    if (FILL) {
        const uint32_t fb = sb + ((U + 2) % 3) * STAGEB;
        fill(fb + offA, fb + offB, pa, pb);
    }
#pragma unroll
    for (int kk = 0; kk < 4; kk++) {
        uint32_t a[2][4];
#pragma unroll
        for (int f = 0; f < 2; f++) {
            uint32_t ad = aA[f][kk & 1] + U * STAGEB + (kk >> 1) * dlt;
            ldsm4(a[f][0], a[f][1], a[f][2], a[f][3], ad);
        }
        uint32_t b[8][2];
#pragma unroll
        for (int p = 0; p < 4; p++) {
            uint32_t bd = aB[p][kk & 1] + U * STAGEB + (kk >> 1) * dlt;
            uint32_t r0, r1, r2, r3;
            ldsm4(r0, r1, r2, r3, bd);
            b[p * 2 + 0][0] = r0; b[p * 2 + 0][1] = r2;
            b[p * 2 + 1][0] = r1; b[p * 2 + 1][1] = r3;
        }
#pragma unroll
        for (int f = 0; f < 2; f++)
#pragma unroll
            for (int n = 0; n < 8; n++)
                mma16816(acc[f][n], a[f], b[n]);
    }
}

__global__ void __launch_bounds__(256, 2) slstm_gemm() {
    extern __shared__ char smem[];
    uint32_t sb = smem_u32(smem);
    const int tid = threadIdx.x;
    const int wid = tid >> 5;
    const int lane = tid & 31;
    const int wm = wid >> 1;            // 0..3  (M warp, 32 rows)
    const int wn = wid & 1;             // 0..1  (N warp, 64 cols)

    // supertile rasterization for L2 reuse
    const int grid_m = BDIM / BM, grid_n = NDIM / BN;   // 32, 128
    const int GROUP = 8;
    int pid = blockIdx.x;
    int npg = GROUP * grid_n;
    int first_m = (pid / npg) * GROUP;
    int gs = min(grid_m - first_m, GROUP);
    int pig = pid % npg;
    int m0 = (first_m + (pig % gs)) * BM;
    int n0 = (pig / gs) * BN;

    // fill-side precompute: per-thread smem offsets + global pointers
    const int frow = tid >> 3;          // 0..31
    const int fc = tid & 7;             // 16B chunk 0..7
    const uint32_t offA = sw_off(frow, fc);
    const uint32_t offB = offA + TILEB;
    const char* pa = (const char*)&g_A[(size_t)(m0 + frow) * KDIM] + fc * 16;
    const char* pb = (const char*)&g_B[(size_t)(n0 + frow) * KDIM] + fc * 16;

    // prologue: fill stages 0,1 into slots 0,1
    fill(sb + 0 * STAGEB + offA, sb + 0 * STAGEB + offB, pa, pb);
    fill(sb + 1 * STAGEB + offA, sb + 1 * STAGEB + offB, pa, pb);

    float acc[2][8][4];
#pragma unroll
    for (int f = 0; f < 2; f++)
#pragma unroll
        for (int n = 0; n < 8; n++)
#pragma unroll
            for (int v = 0; v < 4; v++) acc[f][n][v] = 0.0f;

    const int g = lane >> 3, lr = lane & 7;

    // hoisted swizzled ldmatrix addresses for slot 0, kk=0,1.
    // kk=2,3 = kk-2 address + dlt (bit-6 flip as signed ADD; sign = lane&4).
    uint32_t aA[2][2], aB[4][2];
#pragma unroll
    for (int f = 0; f < 2; f++)
#pragma unroll
        for (int kk = 0; kk < 2; kk++)
            aA[f][kk] = sb + 0 * TILEB +
                        sw_off(wm * 32 + f * 16 + lr + (g & 1) * 8, kk * 2 + (g >> 1));
#pragma unroll
    for (int p = 0; p < 4; p++)
#pragma unroll
        for (int kk = 0; kk < 2; kk++)
            aB[p][kk] = sb + 1 * TILEB +
                        sw_off(wn * 64 + p * 16 + lr + (g & 1) * 8, kk * 2 + (g >> 1));
    const int dlt = (lane & 4) ? -64 : 64;

    // main loop: stages 0..125 (42 x 3 slots), each fills stage s+2
    for (int s3 = 0; s3 < NITER - 2; s3 += 3) {
        gstep<0, 1, true>(sb, offA, offB, pa, pb, aA, aB, dlt, acc);
        gstep<1, 1, true>(sb, offA, offB, pa, pb, aA, aB, dlt, acc);
        gstep<2, 1, true>(sb, offA, offB, pa, pb, aA, aB, dlt, acc);
    }
    // tail: stages 126 (slot 0), 127 (slot 1)
    gstep<0, 1, false>(sb, offA, offB, pa, pb, aA, aB, dlt, acc);
    gstep<1, 0, false>(sb, offA, offB, pa, pb, aA, aB, dlt, acc);

    // epilogue: accum -> g_G
#pragma unroll
    for (int f = 0; f < 2; f++) {
        int rbase = m0 + wm * 32 + f * 16 + (lane >> 2);
#pragma unroll
        for (int n = 0; n < 8; n++) {
            int col = n0 + wn * 64 + n * 8 + (lane & 3) * 2;
            float2 v0 = make_float2(acc[f][n][0], acc[f][n][1]);
            float2 v1 = make_float2(acc[f][n][2], acc[f][n][3]);
            *reinterpret_cast<float2*>(&g_G[(size_t)rbase * NDIM + col]) = v0;
            *reinterpret_cast<float2*>(&g_G[(size_t)(rbase + 8) * NDIM + col]) = v1;
        }
    }
}

// -------------------- elementwise cell epilogue ------------------------------
__device__ __forceinline__ float cell1(float gi, float gf, float go, float gc,
                                       float cv, float mv, float nv,
                                       float& c_new, float& m_new, float& n_new) {
    m_new = fmaxf(gf + mv, gi);
    float i_p = expf(gi - m_new);
    float f_p = expf(gf);                 // faithful: +m_new - m_new cancels
    float o_t = 1.0f / (1.0f + expf(-go));
    float z_t = tanhf(gc);
    c_new = f_p * cv + i_p * z_t;
    n_new = f_p * nv + i_p;
    return o_t * (c_new / n_new);
}

__global__ void __launch_bounds__(256) slstm_cell(
    const float* __restrict__ c, const float* __restrict__ m, const float* __restrict__ n,
    const float* __restrict__ bi, const float* __restrict__ bf, const float* __restrict__ bo,
    const float* __restrict__ bc, float* __restrict__ out) {
    size_t idx = (size_t)blockIdx.x * 256 + threadIdx.x;   // float4 index
    const size_t BD4 = (size_t)BDIM * DDIM / 4;
    size_t b = idx >> 10;
    size_t d4 = idx & 1023;
    const float4* G4 = reinterpret_cast<const float4*>(g_G);
    size_t rowbase = b * (NDIM / 4);
    float4 gi4 = G4[rowbase + 0 * 1024 + d4];
    float4 gf4 = G4[rowbase + 1 * 1024 + d4];
    float4 go4 = G4[rowbase + 2 * 1024 + d4];
    float4 gc4 = G4[rowbase + 3 * 1024 + d4];
    int d = (int)(d4 * 4);
    float4 bi4 = *reinterpret_cast<const float4*>(bi + d);
    float4 bf4 = *reinterpret_cast<const float4*>(bf + d);
    float4 bo4 = *reinterpret_cast<const float4*>(bo + d);
    float4 bc4 = *reinterpret_cast<const float4*>(bc + d);
    float4 c4 = reinterpret_cast<const float4*>(c)[idx];
    float4 m4 = reinterpret_cast<const float4*>(m)[idx];
    float4 n4 = reinterpret_cast<const float4*>(n)[idx];

    float4 h4, cn4, mn4, nn4;
    h4.x = cell1(gi4.x + bi4.x, gf4.x + bf4.x, go4.x + bo4.x, gc4.x + bc4.x, c4.x, m4.x, n4.x, cn4.x, mn4.x, nn4.x);
    h4.y = cell1(gi4.y + bi4.y, gf4.y + bf4.y, go4.y + bo4.y, gc4.y + bc4.y, c4.y, m4.y, n4.y, cn4.y, mn4.y, nn4.y);
    h4.z = cell1(gi4.z + bi4.z, gf4.z + bf4.z, go4.z + bo4.z, gc4.z + bc4.z, c4.z, m4.z, n4.z, cn4.z, mn4.z, nn4.z);
    h4.w = cell1(gi4.w + bi4.w, gf4.w + bf4.w, go4.w + bo4.w, gc4.w + bc4.w, c4.w, m4.w, n4.w, cn4.w, mn4.w, nn4.w);

    float4* o4 = reinterpret_cast<float4*>(out);
    o4[0 * BD4 + idx] = h4;
    o4[1 * BD4 + idx] = cn4;
    o4[2 * BD4 + idx] = mn4;
    o4[3 * BD4 + idx] = nn4;
}

// -------------------- launcher ----------------------------------------------
extern "C" void kernel_launch(void* const* d_in, const int* in_sizes, int n_in,
                              void* d_out, int out_size) {
    (void)in_sizes; (void)n_in; (void)out_size;
    const float* x  = (const float*)d_in[0];
    const float* h  = (const float*)d_in[1];
    const float* c  = (const float*)d_in[2];
    const float* m  = (const float*)d_in[3];
    const float* n  = (const float*)d_in[4];
    const float* wi = (const float*)d_in[5];
    const float* wf = (const float*)d_in[6];
    const float* wo = (const float*)d_in[7];
    const float* wc = (const float*)d_in[8];
    const float* ui = (const float*)d_in[9];
    const float* uf = (const float*)d_in[10];
    const float* uo = (const float*)d_in[11];
    const float* uc = (const float*)d_in[12];
    const float* bi = (const float*)d_in[13];
    const float* bf = (const float*)d_in[14];
    const float* bo = (const float*)d_in[15];
    const float* bc = (const float*)d_in[16];

    cudaFuncSetAttribute(slstm_gemm, cudaFuncAttributeMaxDynamicSharedMemorySize, SMEMB);

    prep_x<<<32768, 256>>>(x);
    prep_h<<<dim3(128, 128), dim3(32, 8)>>>(h);
    prep_w<<<dim3(64, 64, 8), 256>>>(wi, wf, wo, wc, ui, uf, uo, uc);
    slstm_gemm<<<4096, 256, SMEMB>>>();
    slstm_cell<<<16384, 256>>>(c, m, n, bi, bf, bo, bc, (float*)d_out);
}